// round 8
// baseline (speedup 1.0000x reference)
#include <cuda_runtime.h>
#include <cstddef>

#define BB       32
#define LL       32768
#define CC       128
#define KK       64
#define PADL     31          // SAME: out[t] = sum_k x[t+k-31] * w[k]

#define CH       64          // channels per CTA (half)
#define CP       32          // channel pairs per CTA
#define TL       64          // output rows per CTA
#define ROWS     128         // staged x rows: [t0-31, t0+96]
#define NTHREADS 128
#define TSUB     4
#define TT       16          // outputs per thread
#define NTILE    8           // 2-output Winograd tiles per thread
#define NJ       32          // tap chunks (K/2)
#define NU       (NTILE + NJ - 1)   // 39 diagonal steps

#define SMEM_X_F   (ROWS * CH)            // 8192 floats = 32 KB
#define SMEM_G01_F (NJ * CP * 4)          // 4096 floats = 16 KB (g0 pair, -g1 pair)
#define SMEM_GS_F  (NJ * CP * 2)          // 2048 floats =  8 KB (g0+g1 pair)
#define SMEM_BYTES ((SMEM_X_F + SMEM_G01_F + SMEM_GS_F) * 4)   // 57344 B -> 4 CTA/SM

typedef unsigned long long ull;

// Blackwell packed dual-FMA (FFMA2): 2x fp32 FMA per instruction.
__device__ __forceinline__ ull ffma2(ull a, ull b, ull c) {
    ull d;
    asm("fma.rn.f32x2 %0, %1, %2, %3;" : "=l"(d) : "l"(a), "l"(b), "l"(c));
    return d;
}
__device__ __forceinline__ ull pack2(float lo, float hi) {
    ull r;
    asm("mov.b64 %0, {%1, %2};" : "=l"(r) : "f"(lo), "f"(hi));
    return r;
}

// Accurate cheap tanh: exp form + Taylor branch near 0. Error ~1e-6.
__device__ __forceinline__ float fast_tanh(float x) {
    float xc = fminf(fmaxf(x, -15.0f), 15.0f);
    float t  = __expf(2.0f * xc);
    float r  = __fdividef(t - 1.0f, t + 1.0f);
    float x2 = x * x;
    float p  = x * (1.0f + x2 * (-0.33333334f + 0.13333334f * x2));
    return (fabsf(x) < 0.05f) ? p : r;
}

__global__ __launch_bounds__(NTHREADS, 4)
void dwconv1d_tanh_wino_kernel(const float* __restrict__ x,
                               const float* __restrict__ w,     // [K][CC]
                               const float* __restrict__ bias,  // [CC]
                               float* __restrict__ out) {
    extern __shared__ float sm[];
    float*  sx   = sm;                                   // [ROWS][CH]
    float4* g01p = (float4*)(sm + SMEM_X_F);             // [NJ][CP]: (g0.x,g0.y,-g1.x,-g1.y)
    ull*    gsp  = (ull*)(sm + SMEM_X_F + SMEM_G01_F);   // [NJ][CP]: g0+g1 pair

    const int tid  = threadIdx.x;
    const int blk  = blockIdx.x;
    const int half = blk & 1;
    const int tile = (blk >> 1) & 511;       // LL/TL = 512
    const int b    = blk >> 10;
    const int t0   = tile * TL;

    // ---- stage transformed weights: per chunk j, taps (w[2j], w[2j+1]) ----
    {
        #pragma unroll
        for (int n = 0; n < (NJ * CP) / NTHREADS; n++) {   // 8 iters
            int idx = tid + n * NTHREADS;
            int j   = idx >> 5;
            int c   = idx & 31;
            const float2* wr = (const float2*)(w + half * CH) + c;  // pair c of a row
            float2 w0 = wr[(size_t)(2 * j) * (CC / 2)];
            float2 w1 = wr[(size_t)(2 * j + 1) * (CC / 2)];
            g01p[idx] = make_float4(w0.x, w0.y, -w1.x, -w1.y);
            gsp[idx]  = pack2(w0.x + w1.x, w0.y + w1.y);
        }
    }

    // ---- stage x half-rows [t0-31, t0+97), zero-padded ----
    {
        const int base = t0 - PADL;
        const float4* xsrc = (const float4*)(x + (size_t)b * LL * CC); // row = 32 f4
        float4*       xdst = (float4*)sx;                              // row = 16 f4
        #pragma unroll
        for (int n = 0; n < (SMEM_X_F / 4) / NTHREADS; n++) {   // 16 iters
            int idx = tid + n * NTHREADS;        // 0..2047
            int r   = idx >> 4;
            int col = idx & 15;
            int g   = base + r;
            float4 v = make_float4(0.f, 0.f, 0.f, 0.f);
            if ((unsigned)g < (unsigned)LL)
                v = xsrc[(size_t)g * 32 + half * 16 + col];
            xdst[idx] = v;
        }
    }
    __syncthreads();

    const int cp    = tid & (CP - 1);
    const int ts    = tid >> 5;          // 0..3 (warp-uniform)
    const int jbase = ts * TT;           // even

    const ull* px = ((const ull*)sx) + (size_t)jbase * CP + cp;  // row stride CP ull

    // m-domain accumulators; bias folded into M1.
    const float2 bv = ((const float2*)bias)[half * CP + cp];
    const ull bpair = pack2(bv.x, bv.y);
    ull M1[NTILE], M2[NTILE], M3[NTILE];
    #pragma unroll
    for (int t = 0; t < NTILE; t++) { M1[t] = bpair; M2[t] = 0ull; M3[t] = 0ull; }

    // rolling weight windows over chunk j (last 8 entries)
    ull wgs[NTILE], wg0[NTILE], wg1[NTILE];
    const ull NEG1 = pack2(-1.0f, -1.0f);

    // diagonal u = tau + j; rows R = jbase + 2u; d0=X[R], d1=X[R+1], d2=X[R+2]
    ull xc = px[0];                      // X[jbase]
    #pragma unroll
    for (int u = 0; u < NU; u++) {
        ull xa = px[(2 * u + 1) * CP];   // d1
        ull xb = px[(2 * u + 2) * CP];   // d2 (next step's d0)
        ull e0 = ffma2(xa, NEG1, xc);    // d0 - d1
        ull e1 = ffma2(xb, NEG1, xa);    // d1 - d2  (pairs with -g1)
        xc = xb;

        if (u < NJ) {                    // weight chunk j=u enters window
            float4 g = g01p[u * CP + cp];
            wg0[u & (NTILE - 1)] = pack2(g.x, g.y);
            wg1[u & (NTILE - 1)] = pack2(g.z, g.w);
            wgs[u & (NTILE - 1)] = gsp[u * CP + cp];
        }

        #pragma unroll
        for (int tau = 0; tau < NTILE; tau++) {
            if (tau <= u && (u - tau) < NJ) {     // compile-time after unroll
                const int sl = (u - tau) & (NTILE - 1);
                M1[tau] = ffma2(xa, wgs[sl], M1[tau]);
                M2[tau] = ffma2(e0, wg0[sl], M2[tau]);
                M3[tau] = ffma2(e1, wg1[sl], M3[tau]);
            }
        }
    }

    // ---- inverse transform + tanh + store ----
    float2* outp = (float2*)out;                     // row stride CC/2 = 64
    const size_t ob = ((size_t)b * LL + t0 + jbase) * 64 + half * CP + cp;
    #pragma unroll
    for (int tau = 0; tau < NTILE; tau++) {
        float2 a1 = *(float2*)&M1[tau];
        float2 a2 = *(float2*)&M2[tau];
        float2 a3 = *(float2*)&M3[tau];
        float o0x = fast_tanh(a1.x + a2.x);
        float o0y = fast_tanh(a1.y + a2.y);
        float o1x = fast_tanh(a1.x + a3.x);
        float o1y = fast_tanh(a1.y + a3.y);
        outp[ob + (size_t)(2 * tau) * 64]     = make_float2(o0x, o0y);
        outp[ob + (size_t)(2 * tau + 1) * 64] = make_float2(o1x, o1y);
    }
}

extern "C" void kernel_launch(void* const* d_in, const int* in_sizes, int n_in,
                              void* d_out, int out_size) {
    const float* x    = (const float*)d_in[0];
    const float* w    = (const float*)d_in[1];
    const float* bias = (const float*)d_in[2];
    float*       out  = (float*)d_out;

    cudaFuncSetAttribute(dwconv1d_tanh_wino_kernel,
                         cudaFuncAttributeMaxDynamicSharedMemorySize, SMEM_BYTES);

    // grid: b (32) x tile (512) x half (2)
    dwconv1d_tanh_wino_kernel<<<BB * (LL / TL) * 2, NTHREADS, SMEM_BYTES>>>(x, w, bias, out);
}

// round 11
// speedup vs baseline: 1.1044x; 1.1044x over previous
#include <cuda_runtime.h>
#include <cstddef>

#define BB       32
#define LL       32768
#define CC       128
#define KK       64
#define PADL     31          // SAME, K even: out[t] = sum_k x[t+k-31] * w[k]

#define CH       64          // channels per CTA (half of CC)
#define CP       32          // channel pairs per CTA
#define TL       64          // output rows per CTA
#define ROWS     128         // x rows staged: [t0-31, t0+96]
#define NTHREADS 256
#define TSUB     8
#define TT       (TL / TSUB) // 8 outputs per thread

#define SMEM_X_F (ROWS * CH)              // 8192 floats = 32 KB
#define SMEM_W_F (KK * CH)                // 4096 floats = 16 KB
#define SMEM_BYTES ((SMEM_X_F + SMEM_W_F) * 4)   // 49152 B -> 4 CTAs/SM

typedef unsigned long long ull;

// Blackwell packed dual-FMA (FFMA2 in SASS): 2x fp32 FMA per issue.
__device__ __forceinline__ ull ffma2(ull a, ull b, ull c) {
    ull d;
    asm("fma.rn.f32x2 %0, %1, %2, %3;" : "=l"(d) : "l"(a), "l"(b), "l"(c));
    return d;
}
__device__ __forceinline__ ull pack2(float lo, float hi) {
    ull r;
    asm("mov.b64 %0, {%1, %2};" : "=l"(r) : "f"(lo), "f"(hi));
    return r;
}

// tanh(x) = 1 - 2/(e^{2x}+1), 5 instructions, branch-free.
// ex2/rcp approx err ~2^-22 -> abs err ~2e-7. Handles +-inf limits exactly.
__device__ __forceinline__ float tanh5(float x) {
    float s = x * 2.885390082f;        // 2*log2(e)
    float t, r;
    asm("ex2.approx.f32 %0, %1;" : "=f"(t) : "f"(s));
    float d = t + 1.0f;
    asm("rcp.approx.f32 %0, %1;" : "=f"(r) : "f"(d));
    return __fmaf_rn(-2.0f, r, 1.0f);
}

__global__ __launch_bounds__(NTHREADS, 4)
void dwconv1d_tanh_hiocc2_kernel(const float* __restrict__ x,
                                 const float* __restrict__ w,     // [K][CC]
                                 const float* __restrict__ bias,  // [CC]
                                 float* __restrict__ out) {
    extern __shared__ float sm[];
    float* sx = sm;                  // [ROWS][CH]
    float* sw = sm + SMEM_X_F;       // [KK][CH]

    const int tid  = threadIdx.x;
    const int blk  = blockIdx.x;
    const int half = blk & 1;                 // channel half
    const int tile = (blk >> 1) & 511;        // LL/TL = 512 tiles
    const int b    = blk >> 10;
    const int t0   = tile * TL;

    // ---- stage weights half: 64 rows x 16 float4 ----
    {
        const float4* wsrc = (const float4*)w;    // row stride CC/4 = 32
        float4*       wdst = (float4*)sw;
        #pragma unroll
        for (int n = 0; n < (SMEM_W_F / 4) / NTHREADS; n++) {   // 4 iters
            int idx = tid + n * NTHREADS;         // 0..1023
            int k   = idx >> 4;
            int col = idx & 15;
            wdst[idx] = wsrc[k * 32 + half * 16 + col];
        }
    }

    // ---- stage x half-rows [t0-31, t0+97), zero-padded ----
    {
        const int base = t0 - PADL;
        const float4* xsrc = (const float4*)(x + (size_t)b * LL * CC); // row stride 32 f4
        float4*       xdst = (float4*)sx;                              // row stride 16 f4
        #pragma unroll
        for (int n = 0; n < (SMEM_X_F / 4) / NTHREADS; n++) {   // 8 iters
            int idx = tid + n * NTHREADS;         // 0..2047
            int r   = idx >> 4;
            int col = idx & 15;
            int g   = base + r;
            float4 v = make_float4(0.f, 0.f, 0.f, 0.f);
            if ((unsigned)g < (unsigned)LL)
                v = xsrc[(size_t)g * 32 + half * 16 + col];
            xdst[idx] = v;
        }
    }
    __syncthreads();

    const int c2    = tid & (CP - 1);   // channel pair within half
    const int ts    = tid >> 5;         // 0..7 (warp-uniform)
    const int jbase = ts * TT;

    // Immediate-offset LDS bases (row stride CP ull = 256 B).
    const ull* sx2 = ((const ull*)sx) + (size_t)jbase * CP + c2;
    const ull* sw2 = ((const ull*)sw) + c2;

    // bias folded into accumulator init
    const float2 bv = ((const float2*)bias)[half * CP + c2];
    const ull bpair = pack2(bv.x, bv.y);
    ull acc[TT];
    #pragma unroll
    for (int j = 0; j < TT; j++) acc[j] = bpair;

    // Rolling 8-row register window: xw[(k+j)&7] = shared row (jbase+k+j).
    ull xw[TT];
    #pragma unroll
    for (int q = 0; q < TT; q++) xw[q] = sx2[q * CP];

    ull wk = sw2[0];
    #pragma unroll
    for (int k = 0; k < KK; k++) {
        ull wnext = sw2[((k + 1) & (KK - 1)) * CP];
        ull xnew  = sx2[(k + TT) * CP];      // row jbase+k+8 <= 127: in bounds

        #pragma unroll
        for (int j = 0; j < TT; j++)
            acc[j] = ffma2(xw[(k + j) & (TT - 1)], wk, acc[j]);

        xw[k & (TT - 1)] = xnew;
        wk = wnext;
    }

    // ---- tanh + store (8B/lane, coalesced within half) ----
    float2* outp = (float2*)out;          // row stride CC/2 = 64 float2
    const size_t ob = ((size_t)b * LL + t0 + jbase) * 64 + half * CP + c2;
    #pragma unroll
    for (int j = 0; j < TT; j++) {
        float2 a = *(float2*)&acc[j];
        outp[ob + (size_t)j * 64] = make_float2(tanh5(a.x), tanh5(a.y));
    }
}

extern "C" void kernel_launch(void* const* d_in, const int* in_sizes, int n_in,
                              void* d_out, int out_size) {
    const float* x    = (const float*)d_in[0];
    const float* w    = (const float*)d_in[1];
    const float* bias = (const float*)d_in[2];
    float*       out  = (float*)d_out;

    cudaFuncSetAttribute(dwconv1d_tanh_hiocc2_kernel,
                         cudaFuncAttributeMaxDynamicSharedMemorySize, SMEM_BYTES);

    // grid: b (32) x tile (512) x half (2); halves adjacent for L2 halo reuse
    dwconv1d_tanh_hiocc2_kernel<<<BB * (LL / TL) * 2, NTHREADS, SMEM_BYTES>>>(x, w, bias, out);
}